// round 2
// baseline (speedup 1.0000x reference)
#include <cuda_runtime.h>
#include <cuda_bf16.h>

// Problem shape (fixed by the dataset): B=1, H=32, L=8192, D=128
#define H_DIM 32
#define L_DIM 8192
#define D_DIM 128
#define ROWS  (H_DIM * L_DIM)          // 262144 rows per tensor
#define GLOBAL_TOKENS 4

// ---------------------------------------------------------------------------
// Output layout (float32, outputs flattened + concatenated in reference return
// order):
//   kv              (2,1,32,8192,128)  -> K at 0, V at 33,554,432
//   num_insertions  (32,)
//   pos_new         (1,32,8192)
//   kq_new          (1,32,8192,128)
//   k_scales_new    (1,32,8192,1)
//   k_zeros_new     (1,32,8192,1)
//   vq_new          (1,32,8192,128)
//   v_scales_new    (1,32,8192,1)
//   v_zeros_new     (1,32,8192,1)
// ---------------------------------------------------------------------------
#define OFF_K    0ull
#define OFF_V    33554432ull
#define OFF_NINS 67108864ull
#define OFF_POS  67108896ull
#define OFF_KQ   67371040ull
#define OFF_KS   100925472ull
#define OFF_KZ   101187616ull
#define OFF_VQ   101449760ull
#define OFF_VS   135004192ull
#define OFF_VZ   135266336ull

#define SENTINEL 0xFFFFFFFFFFFFFFFFull

// Per-head argmin scratch: packed (orderable_score_bits << 32) | token_index.
// atomicMin gives min score, ties broken toward lowest index (== jnp.argmin
// first-occurrence semantics). Statically initialized to the sentinel; the
// fixup kernel restores the sentinel after consuming it, so every graph
// replay sees the same initial state (deterministic).
__device__ unsigned long long g_argmin[H_DIM] = {
    SENTINEL, SENTINEL, SENTINEL, SENTINEL, SENTINEL, SENTINEL, SENTINEL, SENTINEL,
    SENTINEL, SENTINEL, SENTINEL, SENTINEL, SENTINEL, SENTINEL, SENTINEL, SENTINEL,
    SENTINEL, SENTINEL, SENTINEL, SENTINEL, SENTINEL, SENTINEL, SENTINEL, SENTINEL,
    SENTINEL, SENTINEL, SENTINEL, SENTINEL, SENTINEL, SENTINEL, SENTINEL, SENTINEL
};

// Map float -> uint such that uint ascending order == float ascending order.
__device__ __forceinline__ unsigned int float_orderable(float f) {
    unsigned int b = __float_as_uint(f);
    return (b & 0x80000000u) ? ~b : (b | 0x80000000u);
}

// ---------------------------------------------------------------------------
// Main kernel: one warp per row (K rows first, then V rows).
// Single pass: dequant -> write kv -> (K only: score + argmin atomic)
//              -> min/max -> requant -> write q/scales/zeros.
// ---------------------------------------------------------------------------
__global__ void __launch_bounds__(256)
kv_main_kernel(const int4* __restrict__ kq, const int4* __restrict__ vq,
               const float* __restrict__ ksc, const float* __restrict__ kze,
               const float* __restrict__ vsc, const float* __restrict__ vze,
               const int* __restrict__ pos, const float* __restrict__ w,
               float* __restrict__ out)
{
    const int gwarp = (blockIdx.x * 256 + threadIdx.x) >> 5;   // 0 .. 2*ROWS-1
    const int lane  = threadIdx.x & 31;
    const bool is_k = (gwarp < ROWS);
    const int  r    = is_k ? gwarp : gwarp - ROWS;             // row id

    const int4*  src = is_k ? kq : vq;
    const float  s   = is_k ? ksc[r] : vsc[r];
    const float  z   = is_k ? kze[r] : vze[r];

    // Each lane loads 4 int32 quantized values (16B -> coalesced 512B/warp).
    const int4 q = src[(size_t)r * 32 + lane];

    // Dequantize.
    const float f0 = (float)q.x * s + z;
    const float f1 = (float)q.y * s + z;
    const float f2 = (float)q.z * s + z;
    const float f3 = (float)q.w * s + z;

    // Write dequantized kv output.
    const size_t kvbase = (is_k ? OFF_K : OFF_V) + (size_t)r * 128 + lane * 4;
    *reinterpret_cast<float4*>(out + kvbase) = make_float4(f0, f1, f2, f3);

    // Row min/max (full butterfly -> all lanes hold result).
    float mn = fminf(fminf(f0, f1), fminf(f2, f3));
    float mx = fmaxf(fmaxf(f0, f1), fmaxf(f2, f3));
    #pragma unroll
    for (int o = 16; o > 0; o >>= 1) {
        mn = fminf(mn, __shfl_xor_sync(0xFFFFFFFFu, mn, o));
        mx = fmaxf(mx, __shfl_xor_sync(0xFFFFFFFFu, mx, o));
    }

    // Requantize: one division per row (scale + reciprocal), not per element.
    const float scale = fmaxf((mx - mn) / 15.0f, 1e-6f);
    const float zero  = mn;
    const float inv   = 1.0f / scale;

    const float q0 = fminf(fmaxf(rintf((f0 - zero) * inv), 0.0f), 15.0f);
    const float q1 = fminf(fmaxf(rintf((f1 - zero) * inv), 0.0f), 15.0f);
    const float q2 = fminf(fmaxf(rintf((f2 - zero) * inv), 0.0f), 15.0f);
    const float q3 = fminf(fmaxf(rintf((f3 - zero) * inv), 0.0f), 15.0f);

    const size_t qbase = (is_k ? OFF_KQ : OFF_VQ) + (size_t)r * 128 + lane * 4;
    *reinterpret_cast<float4*>(out + qbase) = make_float4(q0, q1, q2, q3);

    if (lane == 0) {
        out[(is_k ? OFF_KS : OFF_VS) + r] = scale;
        out[(is_k ? OFF_KZ : OFF_VZ) + r] = zero;
    }

    if (is_k) {
        const int h = r >> 13;          // r / 8192
        const int l = r & 8191;         // r % 8192

        // score = dot(dequant_row, w[h])
        const float4 wv =
            *reinterpret_cast<const float4*>(w + (size_t)h * 128 + lane * 4);
        float sc = f0 * wv.x + f1 * wv.y + f2 * wv.z + f3 * wv.w;
        #pragma unroll
        for (int o = 16; o > 0; o >>= 1)
            sc += __shfl_xor_sync(0xFFFFFFFFu, sc, o);

        if (lane == 0) {
            const int p = pos[r];
            out[OFF_POS + r] = (float)p;           // pos_new baseline copy

            float score = sc;
            if (l < GLOBAL_TOKENS) score =  __int_as_float(0x7F800000); // +inf
            if (p == -1)           score = -__int_as_float(0x7F800000); // -inf

            const unsigned long long key =
                ((unsigned long long)float_orderable(score) << 32) |
                (unsigned int)l;
            atomicMin(&g_argmin[h], key);
        }
    }
}

// ---------------------------------------------------------------------------
// Fixup: patch the 32 evicted rows (fill with k_val/v_val, requantize those
// rows, set pos_new/num_insertions). One warp per head. Restores the argmin
// sentinel afterwards so the next graph replay starts clean.
// ---------------------------------------------------------------------------
__device__ __forceinline__ void fill_row(const float4 fv, float* __restrict__ out,
                                         size_t kv_off, size_t q_off,
                                         size_t s_off, size_t z_off,
                                         int r, int lane)
{
    *reinterpret_cast<float4*>(out + kv_off + (size_t)r * 128 + lane * 4) = fv;

    float mn = fminf(fminf(fv.x, fv.y), fminf(fv.z, fv.w));
    float mx = fmaxf(fmaxf(fv.x, fv.y), fmaxf(fv.z, fv.w));
    #pragma unroll
    for (int o = 16; o > 0; o >>= 1) {
        mn = fminf(mn, __shfl_xor_sync(0xFFFFFFFFu, mn, o));
        mx = fmaxf(mx, __shfl_xor_sync(0xFFFFFFFFu, mx, o));
    }
    const float scale = fmaxf((mx - mn) / 15.0f, 1e-6f);
    const float zero  = mn;
    const float inv   = 1.0f / scale;

    const float q0 = fminf(fmaxf(rintf((fv.x - zero) * inv), 0.0f), 15.0f);
    const float q1 = fminf(fmaxf(rintf((fv.y - zero) * inv), 0.0f), 15.0f);
    const float q2 = fminf(fmaxf(rintf((fv.z - zero) * inv), 0.0f), 15.0f);
    const float q3 = fminf(fmaxf(rintf((fv.w - zero) * inv), 0.0f), 15.0f);
    *reinterpret_cast<float4*>(out + q_off + (size_t)r * 128 + lane * 4) =
        make_float4(q0, q1, q2, q3);

    if (lane == 0) {
        out[s_off + r] = scale;
        out[z_off + r] = zero;
    }
}

__global__ void __launch_bounds__(1024)
kv_fixup_kernel(const int* __restrict__ pos, const int* __restrict__ input_pos,
                const float* __restrict__ kval, const float* __restrict__ vval,
                float* __restrict__ out)
{
    const int h    = threadIdx.x >> 5;   // 0..31 (one warp per head)
    const int lane = threadIdx.x & 31;

    const unsigned long long pk = g_argmin[h];
    const int idx = (int)(unsigned int)(pk & 0xFFFFFFFFull);
    const int r   = h * L_DIM + idx;

    if (lane == 0) {
        out[OFF_NINS + h] = (pos[r] == -1) ? 1.0f : 0.0f;
        out[OFF_POS + r]  = (float)input_pos[0];
        g_argmin[h] = SENTINEL;          // reset for next replay
    }

    const float4 kf =
        *reinterpret_cast<const float4*>(kval + (size_t)h * 128 + lane * 4);
    fill_row(kf, out, OFF_K, OFF_KQ, OFF_KS, OFF_KZ, r, lane);

    const float4 vf =
        *reinterpret_cast<const float4*>(vval + (size_t)h * 128 + lane * 4);
    fill_row(vf, out, OFF_V, OFF_VQ, OFF_VS, OFF_VZ, r, lane);
}

// ---------------------------------------------------------------------------
// Launch
// ---------------------------------------------------------------------------
extern "C" void kernel_launch(void* const* d_in, const int* in_sizes, int n_in,
                              void* d_out, int out_size)
{
    const int4*  kq   = (const int4*) d_in[0];   // k_cache_q  int32
    const int4*  vq   = (const int4*) d_in[1];   // v_cache_q  int32
    const float* ksc  = (const float*)d_in[2];   // k_scales
    const float* kze  = (const float*)d_in[3];   // k_zeros
    const float* vsc  = (const float*)d_in[4];   // v_scales
    const float* vze  = (const float*)d_in[5];   // v_zeros
    const int*   pos  = (const int*)  d_in[6];   // pos        int32
    const int*   ipos = (const int*)  d_in[7];   // input_pos  scalar
    const float* kval = (const float*)d_in[8];   // k_val
    const float* vval = (const float*)d_in[9];   // v_val
    const float* w    = (const float*)d_in[10];  // w
    float* out = (float*)d_out;

    // 2*ROWS warps total, 8 warps (256 threads) per block -> 65536 blocks.
    kv_main_kernel<<<(2 * ROWS) / 8, 256>>>(kq, vq, ksc, kze, vsc, vze,
                                            pos, w, out);

    kv_fixup_kernel<<<1, 1024>>>(pos, ipos, kval, vval, out);
}

// round 3
// speedup vs baseline: 2.2949x; 2.2949x over previous
#include <cuda_runtime.h>
#include <cuda_bf16.h>

// Problem shape (fixed by the dataset): B=1, H=32, L=8192, D=128
#define H_DIM 32
#define L_DIM 8192
#define ROWS  (H_DIM * L_DIM)          // 262144 rows per tensor
#define GLOBAL_TOKENS 4

// Output layout (float32, flattened in reference return order)
#define OFF_K    0ull
#define OFF_V    33554432ull
#define OFF_NINS 67108864ull
#define OFF_POS  67108896ull
#define OFF_KQ   67371040ull
#define OFF_KS   100925472ull
#define OFF_KZ   101187616ull
#define OFF_VQ   101449760ull
#define OFF_VS   135004192ull
#define OFF_VZ   135266336ull

// Per-head argmin scratch. We store ~((orderable_score << 32) | token_idx)
// and take atomicMax: max of complement == lexicographic min of (score, idx),
// i.e. jnp.argmin first-occurrence semantics. Max-identity is 0, so the
// default zero-init of a __device__ global is the correct initial state and
// the fixup kernel resets slots to 0 for the next graph replay.
// Slots are strided 16 ull (128B) apart so each head's atomic lands on its
// own L2 line / LTS slice (no cross-head serialization).
__device__ unsigned long long g_argmax[H_DIM * 16];

// Map float -> uint such that uint ascending order == float ascending order.
__device__ __forceinline__ unsigned int float_orderable(float f) {
    unsigned int b = __float_as_uint(f);
    return (b & 0x80000000u) ? ~b : (b | 0x80000000u);
}

__device__ __forceinline__ float4 dequant4(int4 q, float s, float z) {
    return make_float4((float)q.x * s + z, (float)q.y * s + z,
                       (float)q.z * s + z, (float)q.w * s + z);
}

// ---------------------------------------------------------------------------
// Main kernel: one warp per row-pair {2w, 2w+1}, handling BOTH K and V rows.
// 4 front-batched LDG.128 per thread (MLP=4). Single pass:
//   dequant -> write kv -> min/max -> requant -> write q/scales/zeros
//   + (K rows) score dot, block-reduced argmin, ONE atomic per block.
// ---------------------------------------------------------------------------
__global__ void __launch_bounds__(256)
kv_main_kernel(const int4* __restrict__ kq, const int4* __restrict__ vq,
               const float* __restrict__ ksc, const float* __restrict__ kze,
               const float* __restrict__ vsc, const float* __restrict__ vze,
               const int* __restrict__ pos, const float* __restrict__ w,
               float* __restrict__ out)
{
    __shared__ unsigned long long s_key[8];

    const int warp = threadIdx.x >> 5;
    const int lane = threadIdx.x & 31;
    const int wi   = blockIdx.x * 8 + warp;     // 0 .. ROWS/2-1
    const int r0   = wi * 2;
    const int r1   = r0 + 1;
    const int h    = r0 >> 13;                  // same head for whole block

    // ---- front-batched loads (4 wide LDG + scalars) ----
    const int4 a0 = kq[(size_t)r0 * 32 + lane];
    const int4 a1 = kq[(size_t)r1 * 32 + lane];
    const int4 b0 = vq[(size_t)r0 * 32 + lane];
    const int4 b1 = vq[(size_t)r1 * 32 + lane];
    const float ks0 = ksc[r0], ks1 = ksc[r1];
    const float kz0 = kze[r0], kz1 = kze[r1];
    const float vs0 = vsc[r0], vs1 = vsc[r1];
    const float vz0 = vze[r0], vz1 = vze[r1];
    const float4 wv =
        *reinterpret_cast<const float4*>(w + (size_t)h * 128 + lane * 4);
    const int p0 = pos[r0];
    const int p1 = pos[r1];

    // ---- dequantize ----
    const float4 k0 = dequant4(a0, ks0, kz0);
    const float4 k1 = dequant4(a1, ks1, kz1);
    const float4 v0 = dequant4(b0, vs0, vz0);
    const float4 v1 = dequant4(b1, vs1, vz1);

    // ---- write dequantized kv ----
    const int c = lane * 4;
    *reinterpret_cast<float4*>(out + OFF_K + (size_t)r0 * 128 + c) = k0;
    *reinterpret_cast<float4*>(out + OFF_K + (size_t)r1 * 128 + c) = k1;
    *reinterpret_cast<float4*>(out + OFF_V + (size_t)r0 * 128 + c) = v0;
    *reinterpret_cast<float4*>(out + OFF_V + (size_t)r1 * 128 + c) = v1;

    // ---- row min/max (4 rows, combined butterfly) ----
    float mnk0 = fminf(fminf(k0.x, k0.y), fminf(k0.z, k0.w));
    float mxk0 = fmaxf(fmaxf(k0.x, k0.y), fmaxf(k0.z, k0.w));
    float mnk1 = fminf(fminf(k1.x, k1.y), fminf(k1.z, k1.w));
    float mxk1 = fmaxf(fmaxf(k1.x, k1.y), fmaxf(k1.z, k1.w));
    float mnv0 = fminf(fminf(v0.x, v0.y), fminf(v0.z, v0.w));
    float mxv0 = fmaxf(fmaxf(v0.x, v0.y), fmaxf(v0.z, v0.w));
    float mnv1 = fminf(fminf(v1.x, v1.y), fminf(v1.z, v1.w));
    float mxv1 = fmaxf(fmaxf(v1.x, v1.y), fmaxf(v1.z, v1.w));
    // K-row scores (dot with w[h])
    float sc0 = k0.x * wv.x + k0.y * wv.y + k0.z * wv.z + k0.w * wv.w;
    float sc1 = k1.x * wv.x + k1.y * wv.y + k1.z * wv.z + k1.w * wv.w;

    #pragma unroll
    for (int o = 16; o > 0; o >>= 1) {
        mnk0 = fminf(mnk0, __shfl_xor_sync(0xFFFFFFFFu, mnk0, o));
        mxk0 = fmaxf(mxk0, __shfl_xor_sync(0xFFFFFFFFu, mxk0, o));
        mnk1 = fminf(mnk1, __shfl_xor_sync(0xFFFFFFFFu, mnk1, o));
        mxk1 = fmaxf(mxk1, __shfl_xor_sync(0xFFFFFFFFu, mxk1, o));
        mnv0 = fminf(mnv0, __shfl_xor_sync(0xFFFFFFFFu, mnv0, o));
        mxv0 = fmaxf(mxv0, __shfl_xor_sync(0xFFFFFFFFu, mxv0, o));
        mnv1 = fminf(mnv1, __shfl_xor_sync(0xFFFFFFFFu, mnv1, o));
        mxv1 = fmaxf(mxv1, __shfl_xor_sync(0xFFFFFFFFu, mxv1, o));
        sc0 += __shfl_xor_sync(0xFFFFFFFFu, sc0, o);
        sc1 += __shfl_xor_sync(0xFFFFFFFFu, sc1, o);
    }

    // ---- requantize (one reciprocal per row) + write ----
    {
        const float scl = fmaxf((mxk0 - mnk0) / 15.0f, 1e-6f);
        const float inv = 1.0f / scl;
        float4 qv = make_float4(
            fminf(fmaxf(rintf((k0.x - mnk0) * inv), 0.0f), 15.0f),
            fminf(fmaxf(rintf((k0.y - mnk0) * inv), 0.0f), 15.0f),
            fminf(fmaxf(rintf((k0.z - mnk0) * inv), 0.0f), 15.0f),
            fminf(fmaxf(rintf((k0.w - mnk0) * inv), 0.0f), 15.0f));
        *reinterpret_cast<float4*>(out + OFF_KQ + (size_t)r0 * 128 + c) = qv;
        if (lane == 0) { out[OFF_KS + r0] = scl; out[OFF_KZ + r0] = mnk0; }
    }
    {
        const float scl = fmaxf((mxk1 - mnk1) / 15.0f, 1e-6f);
        const float inv = 1.0f / scl;
        float4 qv = make_float4(
            fminf(fmaxf(rintf((k1.x - mnk1) * inv), 0.0f), 15.0f),
            fminf(fmaxf(rintf((k1.y - mnk1) * inv), 0.0f), 15.0f),
            fminf(fmaxf(rintf((k1.z - mnk1) * inv), 0.0f), 15.0f),
            fminf(fmaxf(rintf((k1.w - mnk1) * inv), 0.0f), 15.0f));
        *reinterpret_cast<float4*>(out + OFF_KQ + (size_t)r1 * 128 + c) = qv;
        if (lane == 0) { out[OFF_KS + r1] = scl; out[OFF_KZ + r1] = mnk1; }
    }
    {
        const float scl = fmaxf((mxv0 - mnv0) / 15.0f, 1e-6f);
        const float inv = 1.0f / scl;
        float4 qv = make_float4(
            fminf(fmaxf(rintf((v0.x - mnv0) * inv), 0.0f), 15.0f),
            fminf(fmaxf(rintf((v0.y - mnv0) * inv), 0.0f), 15.0f),
            fminf(fmaxf(rintf((v0.z - mnv0) * inv), 0.0f), 15.0f),
            fminf(fmaxf(rintf((v0.w - mnv0) * inv), 0.0f), 15.0f));
        *reinterpret_cast<float4*>(out + OFF_VQ + (size_t)r0 * 128 + c) = qv;
        if (lane == 0) { out[OFF_VS + r0] = scl; out[OFF_VZ + r0] = mnv0; }
    }
    {
        const float scl = fmaxf((mxv1 - mnv1) / 15.0f, 1e-6f);
        const float inv = 1.0f / scl;
        float4 qv = make_float4(
            fminf(fmaxf(rintf((v1.x - mnv1) * inv), 0.0f), 15.0f),
            fminf(fmaxf(rintf((v1.y - mnv1) * inv), 0.0f), 15.0f),
            fminf(fmaxf(rintf((v1.z - mnv1) * inv), 0.0f), 15.0f),
            fminf(fmaxf(rintf((v1.w - mnv1) * inv), 0.0f), 15.0f));
        *reinterpret_cast<float4*>(out + OFF_VQ + (size_t)r1 * 128 + c) = qv;
        if (lane == 0) { out[OFF_VS + r1] = scl; out[OFF_VZ + r1] = mnv1; }
    }

    // ---- pos_new baseline copy + eviction key (K rows) ----
    const int l0 = r0 & 8191;
    const int l1 = r1 & 8191;
    float score0 = sc0, score1 = sc1;
    if (l0 < GLOBAL_TOKENS) score0 =  __int_as_float(0x7F800000);
    if (p0 == -1)           score0 = -__int_as_float(0x7F800000);
    if (l1 < GLOBAL_TOKENS) score1 =  __int_as_float(0x7F800000);
    if (p1 == -1)           score1 = -__int_as_float(0x7F800000);

    const unsigned long long key0 =
        ~(((unsigned long long)float_orderable(score0) << 32) | (unsigned int)l0);
    const unsigned long long key1 =
        ~(((unsigned long long)float_orderable(score1) << 32) | (unsigned int)l1);

    if (lane == 0) {
        out[OFF_POS + r0] = (float)p0;
        out[OFF_POS + r1] = (float)p1;
        s_key[warp] = (key0 > key1) ? key0 : key1;   // max of complements
    }
    __syncthreads();

    // One atomic per block (16384 total; 512 per head; 128B-strided slots).
    if (threadIdx.x == 0) {
        unsigned long long m = s_key[0];
        #pragma unroll
        for (int i = 1; i < 8; i++) m = (s_key[i] > m) ? s_key[i] : m;
        atomicMax(&g_argmax[h * 16], m);
    }
}

// ---------------------------------------------------------------------------
// Fixup: patch the 32 evicted rows. One warp per head. Resets the argmax
// slot to 0 (the max-identity) for the next graph replay.
// ---------------------------------------------------------------------------
__device__ __forceinline__ void fill_row(const float4 fv, float* __restrict__ out,
                                         size_t kv_off, size_t q_off,
                                         size_t s_off, size_t z_off,
                                         int r, int lane)
{
    *reinterpret_cast<float4*>(out + kv_off + (size_t)r * 128 + lane * 4) = fv;

    float mn = fminf(fminf(fv.x, fv.y), fminf(fv.z, fv.w));
    float mx = fmaxf(fmaxf(fv.x, fv.y), fmaxf(fv.z, fv.w));
    #pragma unroll
    for (int o = 16; o > 0; o >>= 1) {
        mn = fminf(mn, __shfl_xor_sync(0xFFFFFFFFu, mn, o));
        mx = fmaxf(mx, __shfl_xor_sync(0xFFFFFFFFu, mx, o));
    }
    const float scale = fmaxf((mx - mn) / 15.0f, 1e-6f);
    const float zero  = mn;
    const float inv   = 1.0f / scale;

    const float q0 = fminf(fmaxf(rintf((fv.x - zero) * inv), 0.0f), 15.0f);
    const float q1 = fminf(fmaxf(rintf((fv.y - zero) * inv), 0.0f), 15.0f);
    const float q2 = fminf(fmaxf(rintf((fv.z - zero) * inv), 0.0f), 15.0f);
    const float q3 = fminf(fmaxf(rintf((fv.w - zero) * inv), 0.0f), 15.0f);
    *reinterpret_cast<float4*>(out + q_off + (size_t)r * 128 + lane * 4) =
        make_float4(q0, q1, q2, q3);

    if (lane == 0) {
        out[s_off + r] = scale;
        out[z_off + r] = zero;
    }
}

__global__ void __launch_bounds__(1024)
kv_fixup_kernel(const int* __restrict__ pos, const int* __restrict__ input_pos,
                const float* __restrict__ kval, const float* __restrict__ vval,
                float* __restrict__ out)
{
    const int h    = threadIdx.x >> 5;   // 0..31 (one warp per head)
    const int lane = threadIdx.x & 31;

    const unsigned long long pk = ~g_argmax[h * 16];   // back to (score, idx)
    const int idx = (int)(unsigned int)(pk & 0xFFFFFFFFull);
    const int r   = h * L_DIM + idx;

    if (lane == 0) {
        out[OFF_NINS + h] = (pos[r] == -1) ? 1.0f : 0.0f;
        out[OFF_POS + r]  = (float)input_pos[0];
        g_argmax[h * 16]  = 0ull;        // reset for next replay
    }

    const float4 kf =
        *reinterpret_cast<const float4*>(kval + (size_t)h * 128 + lane * 4);
    fill_row(kf, out, OFF_K, OFF_KQ, OFF_KS, OFF_KZ, r, lane);

    const float4 vf =
        *reinterpret_cast<const float4*>(vval + (size_t)h * 128 + lane * 4);
    fill_row(vf, out, OFF_V, OFF_VQ, OFF_VS, OFF_VZ, r, lane);
}

// ---------------------------------------------------------------------------
// Launch
// ---------------------------------------------------------------------------
extern "C" void kernel_launch(void* const* d_in, const int* in_sizes, int n_in,
                              void* d_out, int out_size)
{
    const int4*  kq   = (const int4*) d_in[0];   // k_cache_q  int32
    const int4*  vq   = (const int4*) d_in[1];   // v_cache_q  int32
    const float* ksc  = (const float*)d_in[2];   // k_scales
    const float* kze  = (const float*)d_in[3];   // k_zeros
    const float* vsc  = (const float*)d_in[4];   // v_scales
    const float* vze  = (const float*)d_in[5];   // v_zeros
    const int*   pos  = (const int*)  d_in[6];   // pos        int32
    const int*   ipos = (const int*)  d_in[7];   // input_pos  scalar
    const float* kval = (const float*)d_in[8];   // k_val
    const float* vval = (const float*)d_in[9];   // v_val
    const float* w    = (const float*)d_in[10];  // w
    float* out = (float*)d_out;

    // ROWS/2 warps, 8 warps (256 threads) per block -> 16384 blocks.
    kv_main_kernel<<<ROWS / 16, 256>>>(kq, vq, ksc, kze, vsc, vze,
                                       pos, w, out);

    kv_fixup_kernel<<<1, 1024>>>(pos, ipos, kval, vval, out);
}